// round 13
// baseline (speedup 1.0000x reference)
#include <cuda_runtime.h>
#include <cuda_fp16.h>
#include <math.h>
#include <stdint.h>

#define NN 25000
#define NE 200000
#define NCHUNKS (NE / 32)     // 6250, exact
#define NWARPS  (296 * 8)
#define FULLMASK 0xffffffffu

// ---- scratch (no allocs allowed) ----
__device__ float g_a[NN * 32];    // per-node [a_s(8), a_v(8x3)]
__device__ float g_zc[NN * 2];    // interleaved [z, cnt]

#define INV_SQRT8  0.3535533905932738f
#define DOT_SC     0.5773502691896258f   // 1/sqrt(3)
#define CROSS_SC   0.7071067811865476f   // 1/sqrt(2)
#define OUTS_SC    0.25f                 // 1/sqrt(2*MUL)
#define OUTV_SC    0.2041241452319315f   // 1/sqrt(3*MUL)
#define LOGIT_VSC  0.5773502691896258f   // 1/sqrt(3)
#define LOGIT_SC   0.25f                 // 1/sqrt(2*MUL)

static __device__ __forceinline__ float fsilu(float x) {
    return __fdividef(x, 1.f + __expf(-x));
}
static __device__ __forceinline__ float hsilu(float x) { return fsilu(x) * 0.125f; }

__device__ __forceinline__ uint32_t tf32r(float x) {
    uint32_t v;
    asm("cvt.rna.tf32.f32 %0, %1;" : "=r"(v) : "f"(x));
    return v;
}
__device__ __forceinline__ uint32_t pkh2(float a, float b) {
    __half2 h = __floats2half2_rn(a, b);
    return *(uint32_t*)&h;
}
__device__ __forceinline__ void mma8(float* d, const uint32_t* a, const uint32_t* b) {
    asm volatile("mma.sync.aligned.m16n8k8.row.col.f32.tf32.tf32.f32 "
        "{%0,%1,%2,%3}, {%4,%5,%6,%7}, {%8,%9}, {%0,%1,%2,%3};"
        : "+f"(d[0]), "+f"(d[1]), "+f"(d[2]), "+f"(d[3])
        : "r"(a[0]), "r"(a[1]), "r"(a[2]), "r"(a[3]), "r"(b[0]), "r"(b[1]));
}
__device__ __forceinline__ void mma16(float* d, const uint32_t* a, uint32_t b0, uint32_t b1) {
    asm volatile("mma.sync.aligned.m16n8k16.row.col.f32.f16.f16.f32 "
        "{%0,%1,%2,%3}, {%4,%5,%6,%7}, {%8,%9}, {%0,%1,%2,%3};"
        : "+f"(d[0]), "+f"(d[1]), "+f"(d[2]), "+f"(d[3])
        : "r"(a[0]), "r"(a[1]), "r"(a[2]), "r"(a[3]), "r"(b0), "r"(b1));
}
__device__ __forceinline__ void red2(float* p, float a, float b) {
    asm volatile("red.global.add.v2.f32 [%0], {%1, %2};"
        :: "l"(p), "f"(a), "f"(b) : "memory");
}
__device__ __forceinline__ void pref_l1(const void* p) {
    asm volatile("prefetch.global.L1 [%0];" :: "l"(p));
}

// =====================  small kernels  =====================
__global__ void node_prep(const float* __restrict__ na,
                          const float* __restrict__ Wq0, const float* __restrict__ Wq1,
                          const float* __restrict__ Wd0, const float* __restrict__ Wd1) {
    int i = blockIdx.x * blockDim.x + threadIdx.x;
    if (i >= NN) return;
    float ns[8], nv[8][3];
#pragma unroll
    for (int m = 0; m < 8; m++) ns[m] = na[i * 32 + m];
#pragma unroll
    for (int m = 0; m < 8; m++)
#pragma unroll
        for (int c = 0; c < 3; c++) nv[m][c] = na[i * 32 + 8 + m * 3 + c];
    float qs[8], qv[8][3];
#pragma unroll
    for (int k = 0; k < 8; k++) {
        float a = 0.f;
#pragma unroll
        for (int m = 0; m < 8; m++) a += ns[m] * Wq0[m * 8 + k];
        qs[k] = a * INV_SQRT8;
    }
#pragma unroll
    for (int k = 0; k < 8; k++)
#pragma unroll
        for (int c = 0; c < 3; c++) {
            float a = 0.f;
#pragma unroll
            for (int m = 0; m < 8; m++) a += nv[m][c] * Wq1[m * 8 + k];
            qv[k][c] = a * INV_SQRT8;
        }
#pragma unroll
    for (int n = 0; n < 8; n++) {
        float a = 0.f;
#pragma unroll
        for (int k = 0; k < 8; k++) a += Wd0[k * 8 + n] * qs[k];
        g_a[i * 32 + n] = a;
    }
#pragma unroll
    for (int n = 0; n < 8; n++)
#pragma unroll
        for (int c = 0; c < 3; c++) {
            float a = 0.f;
#pragma unroll
            for (int k = 0; k < 8; k++) a += Wd1[k * 8 + n] * qv[k][c];
            g_a[i * 32 + 8 + n * 3 + c] = a;
        }
}

// coalesced + vectorized: one thread per 4 output elements
__global__ void finalize(float* __restrict__ out) {
    int idx = blockIdx.x * blockDim.x + threadIdx.x;
    if (idx >= NN * 8) return;
    int i = idx >> 3;
    float2 zc = *(const float2*)(g_zc + i * 2);
    float z = zc.x / fmaxf(zc.y, 1.0f);
    float s = (z > 0.f) ? rsqrtf(z) : 0.f;
    float4 v = ((const float4*)out)[idx];
    v.x *= s; v.y *= s; v.z *= s; v.w *= s;
    ((float4*)out)[idx] = v;
}

// =====================  fused single pass  =====================
// smem (u32): W1k frags [1024] | W1v frags [1024] | kW2 frags [10240] | vW2 frags [10240]
#define SW1K_OFF 0
#define SW1V_OFF 1024
#define KB_OFF   2048
#define VB_OFF   12288
#define SMEM_U32 22528
#define SMEM_BYTES (SMEM_U32 * 4)

// layer-2 GEMM of one n-tile: dnt[2][4], K=64 (2 uint4 B loads)
#define GEMM_NT(BP, P, NT, DNT) do {                                             \
    _Pragma("unroll")                                                            \
    for (int q_ = 0; q_ < 4; q_++) { DNT[0][q_] = 0.f; DNT[1][q_] = 0.f; }       \
    _Pragma("unroll")                                                            \
    for (int kkp_ = 0; kkp_ < 2; kkp_++) {                                       \
        uint4 bv_ = (BP)[(((P) * 8 + (NT)) * 2 + kkp_) * 32 + lane];             \
        mma16(DNT[0], &aF[kkp_ * 2][0], bv_.x, bv_.y);                           \
        mma16(DNT[1], &aF[kkp_ * 2][4], bv_.x, bv_.y);                           \
        mma16(DNT[0], &aF[kkp_ * 2 + 1][0], bv_.z, bv_.w);                       \
        mma16(DNT[1], &aF[kkp_ * 2 + 1][4], bv_.z, bv_.w);                       \
    } } while (0)

#define PATH_S(BP, P, FEXPR, T) do {                                             \
    _Pragma("unroll")                                                            \
    for (int nt_ = 0; nt_ < 8; nt_++) {                                          \
        float dnt[2][4];                                                         \
        GEMM_NT(BP, P, nt_, dnt);                                                \
        { int m = nt_; float fv_ = (FEXPR);                                      \
          float f00_ = __shfl_sync(FULLMASK, fv_, r4);                           \
          float f01_ = __shfl_sync(FULLMASK, fv_, 8 + r4);                       \
          float f10_ = __shfl_sync(FULLMASK, fv_, 16 + r4);                      \
          float f11_ = __shfl_sync(FULLMASK, fv_, 24 + r4);                      \
          T[0][0][0] += dnt[0][0] * f00_; T[0][0][1] += dnt[0][1] * f00_;        \
          T[0][1][0] += dnt[0][2] * f01_; T[0][1][1] += dnt[0][3] * f01_;        \
          T[1][0][0] += dnt[1][0] * f10_; T[1][0][1] += dnt[1][1] * f10_;        \
          T[1][1][0] += dnt[1][2] * f11_; T[1][1][1] += dnt[1][3] * f11_; }      \
    } } while (0)

#define PATH_V(BP, P, FX, FY, FZ) do {                                           \
    _Pragma("unroll")                                                            \
    for (int nt_ = 0; nt_ < 8; nt_++) {                                          \
        float dnt[2][4];                                                         \
        GEMM_NT(BP, P, nt_, dnt);                                                \
        { int m = nt_;                                                           \
          float fx_ = (FX), fy_ = (FY), fz_ = (FZ);                              \
          float gx00_ = __shfl_sync(FULLMASK, fx_, r4);                          \
          float gx01_ = __shfl_sync(FULLMASK, fx_, 8 + r4);                      \
          float gx10_ = __shfl_sync(FULLMASK, fx_, 16 + r4);                     \
          float gx11_ = __shfl_sync(FULLMASK, fx_, 24 + r4);                     \
          float gy00_ = __shfl_sync(FULLMASK, fy_, r4);                          \
          float gy01_ = __shfl_sync(FULLMASK, fy_, 8 + r4);                      \
          float gy10_ = __shfl_sync(FULLMASK, fy_, 16 + r4);                     \
          float gy11_ = __shfl_sync(FULLMASK, fy_, 24 + r4);                     \
          float gz00_ = __shfl_sync(FULLMASK, fz_, r4);                          \
          float gz01_ = __shfl_sync(FULLMASK, fz_, 8 + r4);                      \
          float gz10_ = __shfl_sync(FULLMASK, fz_, 16 + r4);                     \
          float gz11_ = __shfl_sync(FULLMASK, fz_, 24 + r4);                     \
          ovA[0][0][0][0] += dnt[0][0] * gx00_; ovA[0][0][1][0] += dnt[0][1] * gx00_; \
          ovA[0][1][0][0] += dnt[0][2] * gx01_; ovA[0][1][1][0] += dnt[0][3] * gx01_; \
          ovA[1][0][0][0] += dnt[1][0] * gx10_; ovA[1][0][1][0] += dnt[1][1] * gx10_; \
          ovA[1][1][0][0] += dnt[1][2] * gx11_; ovA[1][1][1][0] += dnt[1][3] * gx11_; \
          ovA[0][0][0][1] += dnt[0][0] * gy00_; ovA[0][0][1][1] += dnt[0][1] * gy00_; \
          ovA[0][1][0][1] += dnt[0][2] * gy01_; ovA[0][1][1][1] += dnt[0][3] * gy01_; \
          ovA[1][0][0][1] += dnt[1][0] * gy10_; ovA[1][0][1][1] += dnt[1][1] * gy10_; \
          ovA[1][1][0][1] += dnt[1][2] * gy11_; ovA[1][1][1][1] += dnt[1][3] * gy11_; \
          ovA[0][0][0][2] += dnt[0][0] * gz00_; ovA[0][0][1][2] += dnt[0][1] * gz00_; \
          ovA[0][1][0][2] += dnt[0][2] * gz01_; ovA[0][1][1][2] += dnt[0][3] * gz01_; \
          ovA[1][0][0][2] += dnt[1][0] * gz10_; ovA[1][0][1][2] += dnt[1][1] * gz10_; \
          ovA[1][1][0][2] += dnt[1][2] * gz11_; ovA[1][1][1][2] += dnt[1][3] * gz11_; } \
    } } while (0)

// layer-1 GEMM from preloaded a1f; silu+pack into aF
#define RUN_L1(SW) do {                                                          \
    float D1[2][8][4];                                                           \
    _Pragma("unroll")                                                            \
    for (int mt = 0; mt < 2; mt++)                                               \
    _Pragma("unroll")                                                            \
    for (int nt = 0; nt < 8; nt++)                                               \
    _Pragma("unroll")                                                            \
    for (int q = 0; q < 4; q++) D1[mt][nt][q] = 0.f;                             \
    _Pragma("unroll")                                                            \
    for (int nt = 0; nt < 8; nt++)                                               \
    _Pragma("unroll")                                                            \
    for (int kk = 0; kk < 2; kk++) {                                             \
        uint2 bb = (SW)[(nt * 2 + kk) * 32 + lane];                              \
        mma8(D1[0][nt], a1f[0][kk], (const uint32_t*)&bb);                       \
        mma8(D1[1][nt], a1f[1][kk], (const uint32_t*)&bb);                       \
    }                                                                            \
    _Pragma("unroll")                                                            \
    for (int mt = 0; mt < 2; mt++)                                               \
    _Pragma("unroll")                                                            \
    for (int nt = 0; nt < 8; nt++)                                               \
    _Pragma("unroll")                                                            \
    for (int q = 0; q < 4; q++) D1[mt][nt][q] = hsilu(D1[mt][nt][q]);            \
    _Pragma("unroll")                                                            \
    for (int kk = 0; kk < 4; kk++)                                               \
    _Pragma("unroll")                                                            \
    for (int mt = 0; mt < 2; mt++) {                                             \
        aF[kk][mt * 4 + 0] = pkh2(D1[mt][2 * kk][0],     D1[mt][2 * kk][1]);     \
        aF[kk][mt * 4 + 1] = pkh2(D1[mt][2 * kk][2],     D1[mt][2 * kk][3]);     \
        aF[kk][mt * 4 + 2] = pkh2(D1[mt][2 * kk + 1][0], D1[mt][2 * kk + 1][1]); \
        aF[kk][mt * 4 + 3] = pkh2(D1[mt][2 * kk + 1][2], D1[mt][2 * kk + 1][3]); \
    } } while (0)

#define RUN_PATHS(BP, M0, M1) do {                                               \
    const float m0_ = (M0), m1_ = (M1);                                          \
    const float s0A = s0 * m0_;                                                  \
    const float dA  = DOT_SC * m0_;                                              \
    const float s0B = s0 * m1_;                                                  \
    const float cB  = CROSS_SC * m1_;                                            \
    _Pragma("unroll")                                                            \
    for (int a = 0; a < 2; a++)                                                  \
    _Pragma("unroll")                                                            \
    for (int b = 0; b < 2; b++) {                                                \
        osA[a][b][0] = osA[a][b][1] = 0.f;                                       \
        _Pragma("unroll")                                                        \
        for (int p = 0; p < 2; p++)                                              \
            ovA[a][b][p][0] = ovA[a][b][p][1] = ovA[a][b][p][2] = 0.f;           \
    }                                                                            \
    PATH_S(BP, 0, xs[m] * s0A, osA);                                             \
    {                                                                            \
        float t8a[2][2][2];                                                      \
        _Pragma("unroll")                                                        \
        for (int a = 0; a < 2; a++)                                              \
        _Pragma("unroll")                                                        \
        for (int b = 0; b < 2; b++) t8a[a][b][0] = t8a[a][b][1] = 0.f;           \
        PATH_S(BP, 1, xs[m] * m1_, t8a);                                         \
        _Pragma("unroll")                                                        \
        for (int mt = 0; mt < 2; mt++)                                           \
        _Pragma("unroll")                                                        \
        for (int h = 0; h < 2; h++) {                                            \
            int srcl = mt * 16 + h * 8 + r4;                                     \
            float sx = __shfl_sync(FULLMASK, s1x, srcl);                         \
            float sy = __shfl_sync(FULLMASK, s1y, srcl);                         \
            float sz = __shfl_sync(FULLMASK, s1z, srcl);                         \
            ovA[mt][h][0][0] += t8a[mt][h][0] * sx;                              \
            ovA[mt][h][1][0] += t8a[mt][h][1] * sx;                              \
            ovA[mt][h][0][1] += t8a[mt][h][0] * sy;                              \
            ovA[mt][h][1][1] += t8a[mt][h][1] * sy;                              \
            ovA[mt][h][0][2] += t8a[mt][h][0] * sz;                              \
            ovA[mt][h][1][2] += t8a[mt][h][1] * sz;                              \
        }                                                                        \
    }                                                                            \
    PATH_V(BP, 2, xv[m][0] * s0B, xv[m][1] * s0B, xv[m][2] * s0B);               \
    PATH_S(BP, 3, (xv[m][0] * s1x + xv[m][1] * s1y + xv[m][2] * s1z) * dA, osA); \
    PATH_V(BP, 4, (xv[m][1] * s1z - xv[m][2] * s1y) * cB,                        \
                  (xv[m][2] * s1x - xv[m][0] * s1z) * cB,                        \
                  (xv[m][0] * s1y - xv[m][1] * s1x) * cB);                       \
} while (0)

__global__ void __launch_bounds__(256, 2) fused_all(
    const float* __restrict__ na, const int* __restrict__ ei,
    const float* __restrict__ eattr, const float* __restrict__ esh,
    const float* __restrict__ kW1, const float* __restrict__ kW2,
    const float* __restrict__ vW1, const float* __restrict__ vW2,
    float* __restrict__ out) {
    extern __shared__ uint32_t smu[];
    const uint2* sW1k = (const uint2*)(smu + SW1K_OFF);
    const uint2* sW1v = (const uint2*)(smu + SW1V_OFF);
    const uint4* kB = (const uint4*)(smu + KB_OFF);
    const uint4* vB = (const uint4*)(smu + VB_OFF);

    const int tid = threadIdx.x;
    const int wid = tid >> 5;
    const int lane = tid & 31;
    const int r4 = lane >> 2;
    const int qc = lane & 3;

    // stage both W1s as tf32 b-frags (pre-scaled by 1/sqrt(16))
    for (int idx = tid; idx < 512; idx += 256) {
        int lane_ = idx & 31, kk = (idx >> 5) & 1, nt = idx >> 6;
        int r4_ = lane_ >> 2, qc_ = lane_ & 3;
        uint2 a, b;
        a.x = tf32r(kW1[(8 * kk + qc_) * 64 + 8 * nt + r4_] * 0.25f);
        a.y = tf32r(kW1[(8 * kk + 4 + qc_) * 64 + 8 * nt + r4_] * 0.25f);
        ((uint2*)(smu + SW1K_OFF))[idx] = a;
        b.x = tf32r(vW1[(8 * kk + qc_) * 64 + 8 * nt + r4_] * 0.25f);
        b.y = tf32r(vW1[(8 * kk + 4 + qc_) * 64 + 8 * nt + r4_] * 0.25f);
        ((uint2*)(smu + SW1V_OFF))[idx] = b;
    }
    // stage both W2s as fp16 b-frags
    for (int idx = tid; idx < 2560; idx += 256) {
        int lane_ = idx & 31;
        int kkp = (idx >> 5) & 1;
        int nt = (idx >> 6) & 7;
        int p = idx >> 9;
        int col = p * 64 + nt * 8 + (lane_ >> 2);
        int k0 = kkp * 32 + 2 * (lane_ & 3);
        int k1 = k0 + 16;
        uint4 v;
        v.x = pkh2(kW2[k0 * 320 + col],       kW2[(k0 + 1) * 320 + col]);
        v.y = pkh2(kW2[(k0 + 8) * 320 + col], kW2[(k0 + 9) * 320 + col]);
        v.z = pkh2(kW2[k1 * 320 + col],       kW2[(k1 + 1) * 320 + col]);
        v.w = pkh2(kW2[(k1 + 8) * 320 + col], kW2[(k1 + 9) * 320 + col]);
        ((uint4*)(smu + KB_OFF))[idx] = v;
        v.x = pkh2(vW2[k0 * 320 + col],       vW2[(k0 + 1) * 320 + col]);
        v.y = pkh2(vW2[(k0 + 8) * 320 + col], vW2[(k0 + 9) * 320 + col]);
        v.z = pkh2(vW2[k1 * 320 + col],       vW2[(k1 + 1) * 320 + col]);
        v.w = pkh2(vW2[(k1 + 8) * 320 + col], vW2[(k1 + 9) * 320 + col]);
        ((uint4*)(smu + VB_OFF))[idx] = v;
    }
    __syncthreads();   // only barrier in the kernel

    const int gw = blockIdx.x * 8 + wid;
    for (int c = gw; c < NCHUNKS; c += NWARPS) {
        const int e0 = c * 32;
        const int e = e0 + lane;

        // ---- layer-1 A fragments (shared by K and V phases) ----
        uint32_t a1f[2][2][4];
#pragma unroll
        for (int mt = 0; mt < 2; mt++)
#pragma unroll
            for (int kk = 0; kk < 2; kk++) {
                const float* eb0 = eattr + (size_t)(e0 + mt * 16 + r4) * 16 + 8 * kk + qc;
                const float* eb1 = eattr + (size_t)(e0 + mt * 16 + 8 + r4) * 16 + 8 * kk + qc;
                a1f[mt][kk][0] = tf32r(eb0[0]);
                a1f[mt][kk][1] = tf32r(eb1[0]);
                a1f[mt][kk][2] = tf32r(eb0[4]);
                a1f[mt][kk][3] = tf32r(eb1[4]);
            }

        // ---- per-edge features (lane owns edge e) ----
        int srcn = ei[e];
        int dst = ei[NE + e];

        // dstr per accumulator slot + L1 prefetch of g_a rows (hidden under GEMMs)
        int dstr4[2][2];
#pragma unroll
        for (int mt = 0; mt < 2; mt++)
#pragma unroll
            for (int h = 0; h < 2; h++) {
                dstr4[mt][h] = __shfl_sync(FULLMASK, dst, mt * 16 + h * 8 + r4);
                pref_l1(g_a + (size_t)dstr4[mt][h] * 32);
            }

        float xs[8], xv[8][3];
        {
            const float4* xp = (const float4*)(na + (size_t)srcn * 32);
#pragma unroll
            for (int q = 0; q < 2; q++) {
                float4 v = xp[q];
                xs[q * 4 + 0] = v.x; xs[q * 4 + 1] = v.y;
                xs[q * 4 + 2] = v.z; xs[q * 4 + 3] = v.w;
            }
#pragma unroll
            for (int q = 0; q < 6; q++) {
                float4 v = xp[2 + q];
                ((float*)xv)[q * 4 + 0] = v.x; ((float*)xv)[q * 4 + 1] = v.y;
                ((float*)xv)[q * 4 + 2] = v.z; ((float*)xv)[q * 4 + 3] = v.w;
            }
        }
        float4 sh = *(const float4*)(esh + (size_t)e * 4);
        float s0 = sh.x, s1x = sh.y, s1y = sh.z, s1z = sh.w;

        uint32_t aF[4][8];
        float osA[2][2][2];
        float ovA[2][2][2][3];

        // ================= K phase =================
        RUN_L1(sW1k);
        RUN_PATHS(kB, OUTS_SC * LOGIT_SC, OUTV_SC * LOGIT_VSC * LOGIT_SC);

        float ex[2][2];
#pragma unroll
        for (int mt = 0; mt < 2; mt++)
#pragma unroll
            for (int h = 0; h < 2; h++) {
                int dstr = dstr4[mt][h];
                const float* ap = g_a + (size_t)dstr * 32;
                float2 a01 = *(const float2*)(ap + 2 * qc);
                float lp = a01.x * osA[mt][h][0] + a01.y * osA[mt][h][1];
                float2 v0 = *(const float2*)(ap + 8 + 6 * qc);
                float2 v1 = *(const float2*)(ap + 8 + 6 * qc + 2);
                float2 v2 = *(const float2*)(ap + 8 + 6 * qc + 4);
                lp += v0.x * ovA[mt][h][0][0] + v0.y * ovA[mt][h][0][1];
                lp += v1.x * ovA[mt][h][0][2] + v1.y * ovA[mt][h][1][0];
                lp += v2.x * ovA[mt][h][1][1] + v2.y * ovA[mt][h][1][2];
                lp += __shfl_xor_sync(FULLMASK, lp, 1);
                lp += __shfl_xor_sync(FULLMASK, lp, 2);
                float exv = __expf(lp);
                ex[mt][h] = exv;
                if (qc == 0) red2(&g_zc[(size_t)dstr * 2], exv, 1.0f);
            }

        // ================= V phase (att-free: independent of K results) =================
        RUN_L1(sW1v);
        RUN_PATHS(vB, OUTS_SC, OUTV_SC);

#pragma unroll
        for (int mt = 0; mt < 2; mt++)
#pragma unroll
            for (int h = 0; h < 2; h++) {
                float attS = sqrtf(ex[mt][h]);   // per-slot attention weight
                float* ob = out + (size_t)dstr4[mt][h] * 32;
                red2(ob + 2 * qc, attS * osA[mt][h][0], attS * osA[mt][h][1]);
                red2(ob + 8 + 6 * qc,
                     attS * ovA[mt][h][0][0], attS * ovA[mt][h][0][1]);
                red2(ob + 8 + 6 * qc + 2,
                     attS * ovA[mt][h][0][2], attS * ovA[mt][h][1][0]);
                red2(ob + 8 + 6 * qc + 4,
                     attS * ovA[mt][h][1][1], attS * ovA[mt][h][1][2]);
            }
    }
}

extern "C" void kernel_launch(void* const* d_in, const int* in_sizes, int n_in,
                              void* d_out, int out_size) {
    const float* na    = (const float*)d_in[0];
    const int*   ei    = (const int*)d_in[1];
    const float* eattr = (const float*)d_in[2];
    const float* esh   = (const float*)d_in[3];
    const float* Wq0   = (const float*)d_in[4];
    const float* Wq1   = (const float*)d_in[5];
    const float* kW1   = (const float*)d_in[6];
    const float* kW2   = (const float*)d_in[7];
    const float* vW1   = (const float*)d_in[8];
    const float* vW2   = (const float*)d_in[9];
    const float* Wd0   = (const float*)d_in[10];
    const float* Wd1   = (const float*)d_in[11];
    float* out = (float*)d_out;

    cudaFuncSetAttribute(fused_all, cudaFuncAttributeMaxDynamicSharedMemorySize, SMEM_BYTES);

    // zero output + z/cnt via DMA (graph-capturable, no kernel launch)
    void* zc_ptr = nullptr;
    cudaGetSymbolAddress(&zc_ptr, g_zc);
    cudaMemsetAsync(d_out, 0, (size_t)NN * 32 * sizeof(float));
    cudaMemsetAsync(zc_ptr, 0, (size_t)NN * 2 * sizeof(float));

    node_prep<<<(NN + 127) / 128, 128>>>(na, Wq0, Wq1, Wd0, Wd1);
    fused_all<<<296, 256, SMEM_BYTES>>>(na, ei, eattr, esh, kW1, kW2, vW1, vW2, out);
    finalize<<<(NN * 8 + 255) / 256, 256>>>(out);
}

// round 14
// speedup vs baseline: 1.1130x; 1.1130x over previous
#include <cuda_runtime.h>
#include <cuda_fp16.h>
#include <math.h>
#include <stdint.h>

#define NN 25000
#define NE 200000
#define NCHUNKS (NE / 32)     // 6250, exact
#define NWARPS  (296 * 8)
#define FULLMASK 0xffffffffu

// ---- scratch (no allocs allowed) ----
__device__ float g_a[NN * 32];    // per-node [a_s(8), a_v(8x3)]
__device__ float g_zc[NN * 2];    // interleaved [z, cnt]

#define INV_SQRT8  0.3535533905932738f
#define DOT_SC     0.5773502691896258f   // 1/sqrt(3)
#define CROSS_SC   0.7071067811865476f   // 1/sqrt(2)
#define OUTS_SC    0.25f                 // 1/sqrt(2*MUL)
#define OUTV_SC    0.2041241452319315f   // 1/sqrt(3*MUL)
#define LOGIT_VSC  0.5773502691896258f   // 1/sqrt(3)
#define LOGIT_SC   0.25f                 // 1/sqrt(2*MUL)

static __device__ __forceinline__ float fsilu(float x) {
    return __fdividef(x, 1.f + __expf(-x));
}
static __device__ __forceinline__ float hsilu(float x) { return fsilu(x) * 0.125f; }

__device__ __forceinline__ uint32_t tf32r(float x) {
    uint32_t v;
    asm("cvt.rna.tf32.f32 %0, %1;" : "=r"(v) : "f"(x));
    return v;
}
__device__ __forceinline__ uint32_t pkh2(float a, float b) {
    __half2 h = __floats2half2_rn(a, b);
    return *(uint32_t*)&h;
}
__device__ __forceinline__ void mma8(float* d, const uint32_t* a, const uint32_t* b) {
    asm volatile("mma.sync.aligned.m16n8k8.row.col.f32.tf32.tf32.f32 "
        "{%0,%1,%2,%3}, {%4,%5,%6,%7}, {%8,%9}, {%0,%1,%2,%3};"
        : "+f"(d[0]), "+f"(d[1]), "+f"(d[2]), "+f"(d[3])
        : "r"(a[0]), "r"(a[1]), "r"(a[2]), "r"(a[3]), "r"(b[0]), "r"(b[1]));
}
__device__ __forceinline__ void mma16(float* d, const uint32_t* a, uint32_t b0, uint32_t b1) {
    asm volatile("mma.sync.aligned.m16n8k16.row.col.f32.f16.f16.f32 "
        "{%0,%1,%2,%3}, {%4,%5,%6,%7}, {%8,%9}, {%0,%1,%2,%3};"
        : "+f"(d[0]), "+f"(d[1]), "+f"(d[2]), "+f"(d[3])
        : "r"(a[0]), "r"(a[1]), "r"(a[2]), "r"(a[3]), "r"(b0), "r"(b1));
}
__device__ __forceinline__ void red2(float* p, float a, float b) {
    asm volatile("red.global.add.v2.f32 [%0], {%1, %2};"
        :: "l"(p), "f"(a), "f"(b) : "memory");
}

// =====================  small kernels  =====================
// node_prep with coalesced smem staging: 128 nodes per block
__global__ void node_prep(const float* __restrict__ na,
                          const float* __restrict__ Wq0, const float* __restrict__ Wq1,
                          const float* __restrict__ Wd0, const float* __restrict__ Wd1) {
    __shared__ float s[128 * 32];
    const int base = blockIdx.x * 128;
    const int tid = threadIdx.x;

    // coalesced load: 128*32 floats = 1024 float4
    {
        const float4* g = (const float4*)(na + (size_t)base * 32);
        float4* d = (float4*)s;
        int lim = (NN - base) * 8;       // float4 count available
        if (lim > 1024) lim = 1024;
        for (int t = tid; t < lim; t += 128) d[t] = g[t];
    }
    __syncthreads();

    float res[32];
    const int i = base + tid;
    if (i < NN) {
        const float* my = s + tid * 32;
        float ns[8], nv[8][3];
#pragma unroll
        for (int m = 0; m < 8; m++) ns[m] = my[m];
#pragma unroll
        for (int m = 0; m < 8; m++)
#pragma unroll
            for (int c = 0; c < 3; c++) nv[m][c] = my[8 + m * 3 + c];
        float qs[8], qv[8][3];
#pragma unroll
        for (int k = 0; k < 8; k++) {
            float a = 0.f;
#pragma unroll
            for (int m = 0; m < 8; m++) a += ns[m] * Wq0[m * 8 + k];
            qs[k] = a * INV_SQRT8;
        }
#pragma unroll
        for (int k = 0; k < 8; k++)
#pragma unroll
            for (int c = 0; c < 3; c++) {
                float a = 0.f;
#pragma unroll
                for (int m = 0; m < 8; m++) a += nv[m][c] * Wq1[m * 8 + k];
                qv[k][c] = a * INV_SQRT8;
            }
#pragma unroll
        for (int n = 0; n < 8; n++) {
            float a = 0.f;
#pragma unroll
            for (int k = 0; k < 8; k++) a += Wd0[k * 8 + n] * qs[k];
            res[n] = a;
        }
#pragma unroll
        for (int n = 0; n < 8; n++)
#pragma unroll
            for (int c = 0; c < 3; c++) {
                float a = 0.f;
#pragma unroll
                for (int k = 0; k < 8; k++) a += Wd1[k * 8 + n] * qv[k][c];
                res[8 + n * 3 + c] = a;
            }
    }
    __syncthreads();
    if (i < NN) {
        float* my = s + tid * 32;
#pragma unroll
        for (int t = 0; t < 32; t++) my[t] = res[t];
    }
    __syncthreads();
    // coalesced store
    {
        float4* g = (float4*)(g_a + (size_t)base * 32);
        const float4* d = (const float4*)s;
        int lim = (NN - base) * 8;
        if (lim > 1024) lim = 1024;
        for (int t = tid; t < lim; t += 128) g[t] = d[t];
    }
}

// coalesced + vectorized: one thread per 4 output elements
__global__ void finalize(float* __restrict__ out) {
    int idx = blockIdx.x * blockDim.x + threadIdx.x;
    if (idx >= NN * 8) return;
    int i = idx >> 3;
    float2 zc = *(const float2*)(g_zc + i * 2);
    float z = zc.x / fmaxf(zc.y, 1.0f);
    float s = (z > 0.f) ? rsqrtf(z) : 0.f;
    float4 v = ((const float4*)out)[idx];
    v.x *= s; v.y *= s; v.z *= s; v.w *= s;
    ((float4*)out)[idx] = v;
}

// =====================  fused single pass  =====================
// smem (u32): W1k frags [1024] | W1v frags [1024] | kW2 frags [10240] | vW2 frags [10240]
#define SW1K_OFF 0
#define SW1V_OFF 1024
#define KB_OFF   2048
#define VB_OFF   12288
#define SMEM_U32 22528
#define SMEM_BYTES (SMEM_U32 * 4)

// layer-2 GEMM of one n-tile: dnt[2][4], K=64 (2 uint4 B loads)
#define GEMM_NT(BP, P, NT, DNT) do {                                             \
    _Pragma("unroll")                                                            \
    for (int q_ = 0; q_ < 4; q_++) { DNT[0][q_] = 0.f; DNT[1][q_] = 0.f; }       \
    _Pragma("unroll")                                                            \
    for (int kkp_ = 0; kkp_ < 2; kkp_++) {                                       \
        uint4 bv_ = (BP)[(((P) * 8 + (NT)) * 2 + kkp_) * 32 + lane];             \
        mma16(DNT[0], &aF[kkp_ * 2][0], bv_.x, bv_.y);                           \
        mma16(DNT[1], &aF[kkp_ * 2][4], bv_.x, bv_.y);                           \
        mma16(DNT[0], &aF[kkp_ * 2 + 1][0], bv_.z, bv_.w);                       \
        mma16(DNT[1], &aF[kkp_ * 2 + 1][4], bv_.z, bv_.w);                       \
    } } while (0)

#define PATH_S(BP, P, FEXPR, T) do {                                             \
    _Pragma("unroll")                                                            \
    for (int nt_ = 0; nt_ < 8; nt_++) {                                          \
        float dnt[2][4];                                                         \
        GEMM_NT(BP, P, nt_, dnt);                                                \
        { int m = nt_; float fv_ = (FEXPR);                                      \
          float f00_ = __shfl_sync(FULLMASK, fv_, r4);                           \
          float f01_ = __shfl_sync(FULLMASK, fv_, 8 + r4);                       \
          float f10_ = __shfl_sync(FULLMASK, fv_, 16 + r4);                      \
          float f11_ = __shfl_sync(FULLMASK, fv_, 24 + r4);                      \
          T[0][0][0] += dnt[0][0] * f00_; T[0][0][1] += dnt[0][1] * f00_;        \
          T[0][1][0] += dnt[0][2] * f01_; T[0][1][1] += dnt[0][3] * f01_;        \
          T[1][0][0] += dnt[1][0] * f10_; T[1][0][1] += dnt[1][1] * f10_;        \
          T[1][1][0] += dnt[1][2] * f11_; T[1][1][1] += dnt[1][3] * f11_; }      \
    } } while (0)

#define PATH_V(BP, P, FX, FY, FZ) do {                                           \
    _Pragma("unroll")                                                            \
    for (int nt_ = 0; nt_ < 8; nt_++) {                                          \
        float dnt[2][4];                                                         \
        GEMM_NT(BP, P, nt_, dnt);                                                \
        { int m = nt_;                                                           \
          float fx_ = (FX), fy_ = (FY), fz_ = (FZ);                              \
          float gx00_ = __shfl_sync(FULLMASK, fx_, r4);                          \
          float gx01_ = __shfl_sync(FULLMASK, fx_, 8 + r4);                      \
          float gx10_ = __shfl_sync(FULLMASK, fx_, 16 + r4);                     \
          float gx11_ = __shfl_sync(FULLMASK, fx_, 24 + r4);                     \
          float gy00_ = __shfl_sync(FULLMASK, fy_, r4);                          \
          float gy01_ = __shfl_sync(FULLMASK, fy_, 8 + r4);                      \
          float gy10_ = __shfl_sync(FULLMASK, fy_, 16 + r4);                     \
          float gy11_ = __shfl_sync(FULLMASK, fy_, 24 + r4);                     \
          float gz00_ = __shfl_sync(FULLMASK, fz_, r4);                          \
          float gz01_ = __shfl_sync(FULLMASK, fz_, 8 + r4);                      \
          float gz10_ = __shfl_sync(FULLMASK, fz_, 16 + r4);                     \
          float gz11_ = __shfl_sync(FULLMASK, fz_, 24 + r4);                     \
          ovA[0][0][0][0] += dnt[0][0] * gx00_; ovA[0][0][1][0] += dnt[0][1] * gx00_; \
          ovA[0][1][0][0] += dnt[0][2] * gx01_; ovA[0][1][1][0] += dnt[0][3] * gx01_; \
          ovA[1][0][0][0] += dnt[1][0] * gx10_; ovA[1][0][1][0] += dnt[1][1] * gx10_; \
          ovA[1][1][0][0] += dnt[1][2] * gx11_; ovA[1][1][1][0] += dnt[1][3] * gx11_; \
          ovA[0][0][0][1] += dnt[0][0] * gy00_; ovA[0][0][1][1] += dnt[0][1] * gy00_; \
          ovA[0][1][0][1] += dnt[0][2] * gy01_; ovA[0][1][1][1] += dnt[0][3] * gy01_; \
          ovA[1][0][0][1] += dnt[1][0] * gy10_; ovA[1][0][1][1] += dnt[1][1] * gy10_; \
          ovA[1][1][0][1] += dnt[1][2] * gy11_; ovA[1][1][1][1] += dnt[1][3] * gy11_; \
          ovA[0][0][0][2] += dnt[0][0] * gz00_; ovA[0][0][1][2] += dnt[0][1] * gz00_; \
          ovA[0][1][0][2] += dnt[0][2] * gz01_; ovA[0][1][1][2] += dnt[0][3] * gz01_; \
          ovA[1][0][0][2] += dnt[1][0] * gz10_; ovA[1][0][1][2] += dnt[1][1] * gz10_; \
          ovA[1][1][0][2] += dnt[1][2] * gz11_; ovA[1][1][1][2] += dnt[1][3] * gz11_; } \
    } } while (0)

// layer-1 GEMM from preloaded a1f; silu+pack into aF
#define RUN_L1(SW) do {                                                          \
    float D1[2][8][4];                                                           \
    _Pragma("unroll")                                                            \
    for (int mt = 0; mt < 2; mt++)                                               \
    _Pragma("unroll")                                                            \
    for (int nt = 0; nt < 8; nt++)                                               \
    _Pragma("unroll")                                                            \
    for (int q = 0; q < 4; q++) D1[mt][nt][q] = 0.f;                             \
    _Pragma("unroll")                                                            \
    for (int nt = 0; nt < 8; nt++)                                               \
    _Pragma("unroll")                                                            \
    for (int kk = 0; kk < 2; kk++) {                                             \
        uint2 bb = (SW)[(nt * 2 + kk) * 32 + lane];                              \
        mma8(D1[0][nt], a1f[0][kk], (const uint32_t*)&bb);                       \
        mma8(D1[1][nt], a1f[1][kk], (const uint32_t*)&bb);                       \
    }                                                                            \
    _Pragma("unroll")                                                            \
    for (int mt = 0; mt < 2; mt++)                                               \
    _Pragma("unroll")                                                            \
    for (int nt = 0; nt < 8; nt++)                                               \
    _Pragma("unroll")                                                            \
    for (int q = 0; q < 4; q++) D1[mt][nt][q] = hsilu(D1[mt][nt][q]);            \
    _Pragma("unroll")                                                            \
    for (int kk = 0; kk < 4; kk++)                                               \
    _Pragma("unroll")                                                            \
    for (int mt = 0; mt < 2; mt++) {                                             \
        aF[kk][mt * 4 + 0] = pkh2(D1[mt][2 * kk][0],     D1[mt][2 * kk][1]);     \
        aF[kk][mt * 4 + 1] = pkh2(D1[mt][2 * kk][2],     D1[mt][2 * kk][3]);     \
        aF[kk][mt * 4 + 2] = pkh2(D1[mt][2 * kk + 1][0], D1[mt][2 * kk + 1][1]); \
        aF[kk][mt * 4 + 3] = pkh2(D1[mt][2 * kk + 1][2], D1[mt][2 * kk + 1][3]); \
    } } while (0)

#define RUN_PATHS(BP, M0, M1) do {                                               \
    const float m0_ = (M0), m1_ = (M1);                                          \
    const float s0A = s0 * m0_;                                                  \
    const float dA  = DOT_SC * m0_;                                              \
    const float s0B = s0 * m1_;                                                  \
    const float cB  = CROSS_SC * m1_;                                            \
    _Pragma("unroll")                                                            \
    for (int a = 0; a < 2; a++)                                                  \
    _Pragma("unroll")                                                            \
    for (int b = 0; b < 2; b++) {                                                \
        osA[a][b][0] = osA[a][b][1] = 0.f;                                       \
        _Pragma("unroll")                                                        \
        for (int p = 0; p < 2; p++)                                              \
            ovA[a][b][p][0] = ovA[a][b][p][1] = ovA[a][b][p][2] = 0.f;           \
    }                                                                            \
    PATH_S(BP, 0, xs[m] * s0A, osA);                                             \
    {                                                                            \
        float t8a[2][2][2];                                                      \
        _Pragma("unroll")                                                        \
        for (int a = 0; a < 2; a++)                                              \
        _Pragma("unroll")                                                        \
        for (int b = 0; b < 2; b++) t8a[a][b][0] = t8a[a][b][1] = 0.f;           \
        PATH_S(BP, 1, xs[m] * m1_, t8a);                                         \
        _Pragma("unroll")                                                        \
        for (int mt = 0; mt < 2; mt++)                                           \
        _Pragma("unroll")                                                        \
        for (int h = 0; h < 2; h++) {                                            \
            int srcl = mt * 16 + h * 8 + r4;                                     \
            float sx = __shfl_sync(FULLMASK, s1x, srcl);                         \
            float sy = __shfl_sync(FULLMASK, s1y, srcl);                         \
            float sz = __shfl_sync(FULLMASK, s1z, srcl);                         \
            ovA[mt][h][0][0] += t8a[mt][h][0] * sx;                              \
            ovA[mt][h][1][0] += t8a[mt][h][1] * sx;                              \
            ovA[mt][h][0][1] += t8a[mt][h][0] * sy;                              \
            ovA[mt][h][1][1] += t8a[mt][h][1] * sy;                              \
            ovA[mt][h][0][2] += t8a[mt][h][0] * sz;                              \
            ovA[mt][h][1][2] += t8a[mt][h][1] * sz;                              \
        }                                                                        \
    }                                                                            \
    PATH_V(BP, 2, xv[m][0] * s0B, xv[m][1] * s0B, xv[m][2] * s0B);               \
    PATH_S(BP, 3, (xv[m][0] * s1x + xv[m][1] * s1y + xv[m][2] * s1z) * dA, osA); \
    PATH_V(BP, 4, (xv[m][1] * s1z - xv[m][2] * s1y) * cB,                        \
                  (xv[m][2] * s1x - xv[m][0] * s1z) * cB,                        \
                  (xv[m][0] * s1y - xv[m][1] * s1x) * cB);                       \
} while (0)

__global__ void __launch_bounds__(256, 2) fused_all(
    const float* __restrict__ na, const int* __restrict__ ei,
    const float* __restrict__ eattr, const float* __restrict__ esh,
    const float* __restrict__ kW1, const float* __restrict__ kW2,
    const float* __restrict__ vW1, const float* __restrict__ vW2,
    float* __restrict__ out) {
    extern __shared__ uint32_t smu[];
    const uint2* sW1k = (const uint2*)(smu + SW1K_OFF);
    const uint2* sW1v = (const uint2*)(smu + SW1V_OFF);
    const uint4* kB = (const uint4*)(smu + KB_OFF);
    const uint4* vB = (const uint4*)(smu + VB_OFF);

    const int tid = threadIdx.x;
    const int wid = tid >> 5;
    const int lane = tid & 31;
    const int r4 = lane >> 2;
    const int qc = lane & 3;

    // stage both W1s as tf32 b-frags (pre-scaled by 1/sqrt(16))
    for (int idx = tid; idx < 512; idx += 256) {
        int lane_ = idx & 31, kk = (idx >> 5) & 1, nt = idx >> 6;
        int r4_ = lane_ >> 2, qc_ = lane_ & 3;
        uint2 a, b;
        a.x = tf32r(kW1[(8 * kk + qc_) * 64 + 8 * nt + r4_] * 0.25f);
        a.y = tf32r(kW1[(8 * kk + 4 + qc_) * 64 + 8 * nt + r4_] * 0.25f);
        ((uint2*)(smu + SW1K_OFF))[idx] = a;
        b.x = tf32r(vW1[(8 * kk + qc_) * 64 + 8 * nt + r4_] * 0.25f);
        b.y = tf32r(vW1[(8 * kk + 4 + qc_) * 64 + 8 * nt + r4_] * 0.25f);
        ((uint2*)(smu + SW1V_OFF))[idx] = b;
    }
    // stage both W2s as fp16 b-frags
    for (int idx = tid; idx < 2560; idx += 256) {
        int lane_ = idx & 31;
        int kkp = (idx >> 5) & 1;
        int nt = (idx >> 6) & 7;
        int p = idx >> 9;
        int col = p * 64 + nt * 8 + (lane_ >> 2);
        int k0 = kkp * 32 + 2 * (lane_ & 3);
        int k1 = k0 + 16;
        uint4 v;
        v.x = pkh2(kW2[k0 * 320 + col],       kW2[(k0 + 1) * 320 + col]);
        v.y = pkh2(kW2[(k0 + 8) * 320 + col], kW2[(k0 + 9) * 320 + col]);
        v.z = pkh2(kW2[k1 * 320 + col],       kW2[(k1 + 1) * 320 + col]);
        v.w = pkh2(kW2[(k1 + 8) * 320 + col], kW2[(k1 + 9) * 320 + col]);
        ((uint4*)(smu + KB_OFF))[idx] = v;
        v.x = pkh2(vW2[k0 * 320 + col],       vW2[(k0 + 1) * 320 + col]);
        v.y = pkh2(vW2[(k0 + 8) * 320 + col], vW2[(k0 + 9) * 320 + col]);
        v.z = pkh2(vW2[k1 * 320 + col],       vW2[(k1 + 1) * 320 + col]);
        v.w = pkh2(vW2[(k1 + 8) * 320 + col], vW2[(k1 + 9) * 320 + col]);
        ((uint4*)(smu + VB_OFF))[idx] = v;
    }
    __syncthreads();   // only barrier in the kernel

    const int gw = blockIdx.x * 8 + wid;
    for (int c = gw; c < NCHUNKS; c += NWARPS) {
        const int e0 = c * 32;
        const int e = e0 + lane;

        // ---- layer-1 A fragments (shared by K and V phases) ----
        uint32_t a1f[2][2][4];
#pragma unroll
        for (int mt = 0; mt < 2; mt++)
#pragma unroll
            for (int kk = 0; kk < 2; kk++) {
                const float* eb0 = eattr + (size_t)(e0 + mt * 16 + r4) * 16 + 8 * kk + qc;
                const float* eb1 = eattr + (size_t)(e0 + mt * 16 + 8 + r4) * 16 + 8 * kk + qc;
                a1f[mt][kk][0] = tf32r(eb0[0]);
                a1f[mt][kk][1] = tf32r(eb1[0]);
                a1f[mt][kk][2] = tf32r(eb0[4]);
                a1f[mt][kk][3] = tf32r(eb1[4]);
            }

        // ---- per-edge features (lane owns edge e) ----
        int srcn = ei[e];
        int dst = ei[NE + e];
        float xs[8], xv[8][3];
        {
            const float4* xp = (const float4*)(na + (size_t)srcn * 32);
#pragma unroll
            for (int q = 0; q < 2; q++) {
                float4 v = xp[q];
                xs[q * 4 + 0] = v.x; xs[q * 4 + 1] = v.y;
                xs[q * 4 + 2] = v.z; xs[q * 4 + 3] = v.w;
            }
#pragma unroll
            for (int q = 0; q < 6; q++) {
                float4 v = xp[2 + q];
                ((float*)xv)[q * 4 + 0] = v.x; ((float*)xv)[q * 4 + 1] = v.y;
                ((float*)xv)[q * 4 + 2] = v.z; ((float*)xv)[q * 4 + 3] = v.w;
            }
        }
        float4 sh = *(const float4*)(esh + (size_t)e * 4);
        float s0 = sh.x, s1x = sh.y, s1y = sh.z, s1z = sh.w;

        uint32_t aF[4][8];
        float osA[2][2][2];
        float ovA[2][2][2][3];

        // ================= K phase =================
        RUN_L1(sW1k);
        RUN_PATHS(kB, OUTS_SC * LOGIT_SC, OUTV_SC * LOGIT_VSC * LOGIT_SC);

        float ex[2][2];
#pragma unroll
        for (int mt = 0; mt < 2; mt++)
#pragma unroll
            for (int h = 0; h < 2; h++) {
                int srcl = mt * 16 + h * 8 + r4;
                int dstr = __shfl_sync(FULLMASK, dst, srcl);
                const float* ap = g_a + (size_t)dstr * 32;
                float2 a01 = *(const float2*)(ap + 2 * qc);
                float lp = a01.x * osA[mt][h][0] + a01.y * osA[mt][h][1];
                float2 v0 = *(const float2*)(ap + 8 + 6 * qc);
                float2 v1 = *(const float2*)(ap + 8 + 6 * qc + 2);
                float2 v2 = *(const float2*)(ap + 8 + 6 * qc + 4);
                lp += v0.x * ovA[mt][h][0][0] + v0.y * ovA[mt][h][0][1];
                lp += v1.x * ovA[mt][h][0][2] + v1.y * ovA[mt][h][1][0];
                lp += v2.x * ovA[mt][h][1][1] + v2.y * ovA[mt][h][1][2];
                lp += __shfl_xor_sync(FULLMASK, lp, 1);
                lp += __shfl_xor_sync(FULLMASK, lp, 2);
                float exv = __expf(lp);
                ex[mt][h] = exv;
                if (qc == 0) red2(&g_zc[(size_t)dstr * 2], exv, 1.0f);
            }

        // hand att = sqrt(ex of MY edge) back to the owner lane
        float att = 0.f;
#pragma unroll
        for (int mt = 0; mt < 2; mt++)
#pragma unroll
            for (int h = 0; h < 2; h++) {
                float v = __shfl_sync(FULLMASK, ex[mt][h], 4 * (lane & 7));
                if ((lane >> 3) == mt * 2 + h) att = sqrtf(v);
            }

        // ================= V phase =================
        RUN_L1(sW1v);
        RUN_PATHS(vB, att * OUTS_SC, att * OUTV_SC);

#pragma unroll
        for (int mt = 0; mt < 2; mt++)
#pragma unroll
            for (int h = 0; h < 2; h++) {
                int srcl = mt * 16 + h * 8 + r4;
                int dstr = __shfl_sync(FULLMASK, dst, srcl);
                float* ob = out + (size_t)dstr * 32;
                red2(ob + 2 * qc, osA[mt][h][0], osA[mt][h][1]);
                red2(ob + 8 + 6 * qc,     ovA[mt][h][0][0], ovA[mt][h][0][1]);
                red2(ob + 8 + 6 * qc + 2, ovA[mt][h][0][2], ovA[mt][h][1][0]);
                red2(ob + 8 + 6 * qc + 4, ovA[mt][h][1][1], ovA[mt][h][1][2]);
            }
    }
}

extern "C" void kernel_launch(void* const* d_in, const int* in_sizes, int n_in,
                              void* d_out, int out_size) {
    const float* na    = (const float*)d_in[0];
    const int*   ei    = (const int*)d_in[1];
    const float* eattr = (const float*)d_in[2];
    const float* esh   = (const float*)d_in[3];
    const float* Wq0   = (const float*)d_in[4];
    const float* Wq1   = (const float*)d_in[5];
    const float* kW1   = (const float*)d_in[6];
    const float* kW2   = (const float*)d_in[7];
    const float* vW1   = (const float*)d_in[8];
    const float* vW2   = (const float*)d_in[9];
    const float* Wd0   = (const float*)d_in[10];
    const float* Wd1   = (const float*)d_in[11];
    float* out = (float*)d_out;

    cudaFuncSetAttribute(fused_all, cudaFuncAttributeMaxDynamicSharedMemorySize, SMEM_BYTES);

    // zero output + z/cnt via DMA (graph-capturable, no kernel launch)
    void* zc_ptr = nullptr;
    cudaGetSymbolAddress(&zc_ptr, g_zc);
    cudaMemsetAsync(d_out, 0, (size_t)NN * 32 * sizeof(float));
    cudaMemsetAsync(zc_ptr, 0, (size_t)NN * 2 * sizeof(float));

    node_prep<<<(NN + 127) / 128, 128>>>(na, Wq0, Wq1, Wd0, Wd1);
    fused_all<<<296, 256, SMEM_BYTES>>>(na, ei, eattr, esh, kW1, kW2, vW1, vW2, out);
    finalize<<<(NN * 8 + 255) / 256, 256>>>(out);
}

// round 15
// speedup vs baseline: 1.1506x; 1.0338x over previous
#include <cuda_runtime.h>
#include <cuda_fp16.h>
#include <math.h>
#include <stdint.h>

#define NN 25000
#define NE 200000
#define NCHUNKS (NE / 32)     // 6250, exact
#define GRID_FA 304           // 2 x 152 SMs (GB300)
#define NWARPS  (GRID_FA * 8)
#define FULLMASK 0xffffffffu

// ---- scratch (no allocs allowed) ----
__device__ float g_a[NN * 32];    // per-node [a_s(8), a_v(8x3)]
__device__ float g_zc[NN * 2];    // interleaved [z, cnt]

#define INV_SQRT8  0.3535533905932738f
#define DOT_SC     0.5773502691896258f   // 1/sqrt(3)
#define CROSS_SC   0.7071067811865476f   // 1/sqrt(2)
#define OUTS_SC    0.25f                 // 1/sqrt(2*MUL)
#define OUTV_SC    0.2041241452319315f   // 1/sqrt(3*MUL)
#define LOGIT_VSC  0.5773502691896258f   // 1/sqrt(3)
#define LOGIT_SC   0.25f                 // 1/sqrt(2*MUL)

static __device__ __forceinline__ float fsilu(float x) {
    return __fdividef(x, 1.f + __expf(-x));
}
static __device__ __forceinline__ float hsilu(float x) { return fsilu(x) * 0.125f; }

__device__ __forceinline__ uint32_t tf32r(float x) {
    uint32_t v;
    asm("cvt.rna.tf32.f32 %0, %1;" : "=r"(v) : "f"(x));
    return v;
}
__device__ __forceinline__ uint32_t pkh2(float a, float b) {
    __half2 h = __floats2half2_rn(a, b);
    return *(uint32_t*)&h;
}
__device__ __forceinline__ void mma8(float* d, const uint32_t* a, const uint32_t* b) {
    asm volatile("mma.sync.aligned.m16n8k8.row.col.f32.tf32.tf32.f32 "
        "{%0,%1,%2,%3}, {%4,%5,%6,%7}, {%8,%9}, {%0,%1,%2,%3};"
        : "+f"(d[0]), "+f"(d[1]), "+f"(d[2]), "+f"(d[3])
        : "r"(a[0]), "r"(a[1]), "r"(a[2]), "r"(a[3]), "r"(b[0]), "r"(b[1]));
}
__device__ __forceinline__ void mma16(float* d, const uint32_t* a, uint32_t b0, uint32_t b1) {
    asm volatile("mma.sync.aligned.m16n8k16.row.col.f32.f16.f16.f32 "
        "{%0,%1,%2,%3}, {%4,%5,%6,%7}, {%8,%9}, {%0,%1,%2,%3};"
        : "+f"(d[0]), "+f"(d[1]), "+f"(d[2]), "+f"(d[3])
        : "r"(a[0]), "r"(a[1]), "r"(a[2]), "r"(a[3]), "r"(b0), "r"(b1));
}
__device__ __forceinline__ void red2(float* p, float a, float b) {
    asm volatile("red.global.add.v2.f32 [%0], {%1, %2};"
        :: "l"(p), "f"(a), "f"(b) : "memory");
}

// =====================  small kernels  =====================
// node_prep: 4 threads per node (role 0 = scalar channel, roles 1-3 = vector comps)
__global__ void node_prep(const float* __restrict__ na,
                          const float* __restrict__ Wq0, const float* __restrict__ Wq1,
                          const float* __restrict__ Wd0, const float* __restrict__ Wd1) {
    __shared__ float si[64 * 33];
    __shared__ float so[64 * 33];
    const int base = blockIdx.x * 64;
    const int tid = threadIdx.x;

    int navail = NN - base; if (navail > 64) navail = 64;
    const int avail = navail * 32;
    for (int t = tid; t < avail; t += 256)
        si[(t >> 5) * 33 + (t & 31)] = na[(size_t)base * 32 + t];
    __syncthreads();

    const int node = tid >> 2;
    const int role = tid & 3;
    const int i = base + node;
    float res[8];
    if (i < NN) {
        const float* my = si + node * 33;
        const float* W1p = (role == 0) ? Wq0 : Wq1;
        const float* W2p = (role == 0) ? Wd0 : Wd1;
        const int soff = (role == 0) ? 0 : 8 + (role - 1);
        const int sstr = (role == 0) ? 1 : 3;
        float x[8];
#pragma unroll
        for (int m = 0; m < 8; m++) x[m] = my[soff + m * sstr];
        float q[8];
#pragma unroll
        for (int k = 0; k < 8; k++) {
            float a = 0.f;
#pragma unroll
            for (int m = 0; m < 8; m++) a += x[m] * W1p[m * 8 + k];
            q[k] = a * INV_SQRT8;
        }
#pragma unroll
        for (int n = 0; n < 8; n++) {
            float a = 0.f;
#pragma unroll
            for (int k = 0; k < 8; k++) a += W2p[k * 8 + n] * q[k];
            res[n] = a;
        }
        float* o = so + node * 33;
#pragma unroll
        for (int n = 0; n < 8; n++) o[soff + n * sstr] = res[n];
    }
    __syncthreads();
    for (int t = tid; t < avail; t += 256)
        g_a[(size_t)base * 32 + t] = so[(t >> 5) * 33 + (t & 31)];
}

// coalesced + vectorized: one thread per 4 output elements
__global__ void finalize(float* __restrict__ out) {
    int idx = blockIdx.x * blockDim.x + threadIdx.x;
    if (idx >= NN * 8) return;
    int i = idx >> 3;
    float2 zc = *(const float2*)(g_zc + i * 2);
    float z = zc.x / fmaxf(zc.y, 1.0f);
    float s = (z > 0.f) ? rsqrtf(z) : 0.f;
    float4 v = ((const float4*)out)[idx];
    v.x *= s; v.y *= s; v.z *= s; v.w *= s;
    ((float4*)out)[idx] = v;
}

// =====================  fused single pass  =====================
// smem (u32): W1k frags [1024] | W1v frags [1024] | kW2 frags [10240] | vW2 frags [10240]
#define SW1K_OFF 0
#define SW1V_OFF 1024
#define KB_OFF   2048
#define VB_OFF   12288
#define SMEM_U32 22528
#define SMEM_BYTES (SMEM_U32 * 4)

// layer-2 GEMM of one n-tile: dnt[2][4], K=64 (2 uint4 B loads)
#define GEMM_NT(BP, P, NT, DNT) do {                                             \
    _Pragma("unroll")                                                            \
    for (int q_ = 0; q_ < 4; q_++) { DNT[0][q_] = 0.f; DNT[1][q_] = 0.f; }       \
    _Pragma("unroll")                                                            \
    for (int kkp_ = 0; kkp_ < 2; kkp_++) {                                       \
        uint4 bv_ = (BP)[(((P) * 8 + (NT)) * 2 + kkp_) * 32 + lane];             \
        mma16(DNT[0], &aF[kkp_ * 2][0], bv_.x, bv_.y);                           \
        mma16(DNT[1], &aF[kkp_ * 2][4], bv_.x, bv_.y);                           \
        mma16(DNT[0], &aF[kkp_ * 2 + 1][0], bv_.z, bv_.w);                       \
        mma16(DNT[1], &aF[kkp_ * 2 + 1][4], bv_.z, bv_.w);                       \
    } } while (0)

#define PATH_S(BP, P, FEXPR, T) do {                                             \
    _Pragma("unroll")                                                            \
    for (int nt_ = 0; nt_ < 8; nt_++) {                                          \
        float dnt[2][4];                                                         \
        GEMM_NT(BP, P, nt_, dnt);                                                \
        { int m = nt_; float fv_ = (FEXPR);                                      \
          float f00_ = __shfl_sync(FULLMASK, fv_, r4);                           \
          float f01_ = __shfl_sync(FULLMASK, fv_, 8 + r4);                       \
          float f10_ = __shfl_sync(FULLMASK, fv_, 16 + r4);                      \
          float f11_ = __shfl_sync(FULLMASK, fv_, 24 + r4);                      \
          T[0][0][0] += dnt[0][0] * f00_; T[0][0][1] += dnt[0][1] * f00_;        \
          T[0][1][0] += dnt[0][2] * f01_; T[0][1][1] += dnt[0][3] * f01_;        \
          T[1][0][0] += dnt[1][0] * f10_; T[1][0][1] += dnt[1][1] * f10_;        \
          T[1][1][0] += dnt[1][2] * f11_; T[1][1][1] += dnt[1][3] * f11_; }      \
    } } while (0)

#define PATH_V(BP, P, FX, FY, FZ) do {                                           \
    _Pragma("unroll")                                                            \
    for (int nt_ = 0; nt_ < 8; nt_++) {                                          \
        float dnt[2][4];                                                         \
        GEMM_NT(BP, P, nt_, dnt);                                                \
        { int m = nt_;                                                           \
          float fx_ = (FX), fy_ = (FY), fz_ = (FZ);                              \
          float gx00_ = __shfl_sync(FULLMASK, fx_, r4);                          \
          float gx01_ = __shfl_sync(FULLMASK, fx_, 8 + r4);                      \
          float gx10_ = __shfl_sync(FULLMASK, fx_, 16 + r4);                     \
          float gx11_ = __shfl_sync(FULLMASK, fx_, 24 + r4);                     \
          float gy00_ = __shfl_sync(FULLMASK, fy_, r4);                          \
          float gy01_ = __shfl_sync(FULLMASK, fy_, 8 + r4);                      \
          float gy10_ = __shfl_sync(FULLMASK, fy_, 16 + r4);                     \
          float gy11_ = __shfl_sync(FULLMASK, fy_, 24 + r4);                     \
          float gz00_ = __shfl_sync(FULLMASK, fz_, r4);                          \
          float gz01_ = __shfl_sync(FULLMASK, fz_, 8 + r4);                      \
          float gz10_ = __shfl_sync(FULLMASK, fz_, 16 + r4);                     \
          float gz11_ = __shfl_sync(FULLMASK, fz_, 24 + r4);                     \
          ovA[0][0][0][0] += dnt[0][0] * gx00_; ovA[0][0][1][0] += dnt[0][1] * gx00_; \
          ovA[0][1][0][0] += dnt[0][2] * gx01_; ovA[0][1][1][0] += dnt[0][3] * gx01_; \
          ovA[1][0][0][0] += dnt[1][0] * gx10_; ovA[1][0][1][0] += dnt[1][1] * gx10_; \
          ovA[1][1][0][0] += dnt[1][2] * gx11_; ovA[1][1][1][0] += dnt[1][3] * gx11_; \
          ovA[0][0][0][1] += dnt[0][0] * gy00_; ovA[0][0][1][1] += dnt[0][1] * gy00_; \
          ovA[0][1][0][1] += dnt[0][2] * gy01_; ovA[0][1][1][1] += dnt[0][3] * gy01_; \
          ovA[1][0][0][1] += dnt[1][0] * gy10_; ovA[1][0][1][1] += dnt[1][1] * gy10_; \
          ovA[1][1][0][1] += dnt[1][2] * gy11_; ovA[1][1][1][1] += dnt[1][3] * gy11_; \
          ovA[0][0][0][2] += dnt[0][0] * gz00_; ovA[0][0][1][2] += dnt[0][1] * gz00_; \
          ovA[0][1][0][2] += dnt[0][2] * gz01_; ovA[0][1][1][2] += dnt[0][3] * gz01_; \
          ovA[1][0][0][2] += dnt[1][0] * gz10_; ovA[1][0][1][2] += dnt[1][1] * gz10_; \
          ovA[1][1][0][2] += dnt[1][2] * gz11_; ovA[1][1][1][2] += dnt[1][3] * gz11_; } \
    } } while (0)

// layer-1 GEMM from preloaded a1f; silu+pack into aF
#define RUN_L1(SW) do {                                                          \
    float D1[2][8][4];                                                           \
    _Pragma("unroll")                                                            \
    for (int mt = 0; mt < 2; mt++)                                               \
    _Pragma("unroll")                                                            \
    for (int nt = 0; nt < 8; nt++)                                               \
    _Pragma("unroll")                                                            \
    for (int q = 0; q < 4; q++) D1[mt][nt][q] = 0.f;                             \
    _Pragma("unroll")                                                            \
    for (int nt = 0; nt < 8; nt++)                                               \
    _Pragma("unroll")                                                            \
    for (int kk = 0; kk < 2; kk++) {                                             \
        uint2 bb = (SW)[(nt * 2 + kk) * 32 + lane];                              \
        mma8(D1[0][nt], a1f[0][kk], (const uint32_t*)&bb);                       \
        mma8(D1[1][nt], a1f[1][kk], (const uint32_t*)&bb);                       \
    }                                                                            \
    _Pragma("unroll")                                                            \
    for (int mt = 0; mt < 2; mt++)                                               \
    _Pragma("unroll")                                                            \
    for (int nt = 0; nt < 8; nt++)                                               \
    _Pragma("unroll")                                                            \
    for (int q = 0; q < 4; q++) D1[mt][nt][q] = hsilu(D1[mt][nt][q]);            \
    _Pragma("unroll")                                                            \
    for (int kk = 0; kk < 4; kk++)                                               \
    _Pragma("unroll")                                                            \
    for (int mt = 0; mt < 2; mt++) {                                             \
        aF[kk][mt * 4 + 0] = pkh2(D1[mt][2 * kk][0],     D1[mt][2 * kk][1]);     \
        aF[kk][mt * 4 + 1] = pkh2(D1[mt][2 * kk][2],     D1[mt][2 * kk][3]);     \
        aF[kk][mt * 4 + 2] = pkh2(D1[mt][2 * kk + 1][0], D1[mt][2 * kk + 1][1]); \
        aF[kk][mt * 4 + 3] = pkh2(D1[mt][2 * kk + 1][2], D1[mt][2 * kk + 1][3]); \
    } } while (0)

#define RUN_PATHS(BP, M0, M1) do {                                               \
    const float m0_ = (M0), m1_ = (M1);                                          \
    const float s0A = s0 * m0_;                                                  \
    const float dA  = DOT_SC * m0_;                                              \
    const float s0B = s0 * m1_;                                                  \
    const float cB  = CROSS_SC * m1_;                                            \
    _Pragma("unroll")                                                            \
    for (int a = 0; a < 2; a++)                                                  \
    _Pragma("unroll")                                                            \
    for (int b = 0; b < 2; b++) {                                                \
        osA[a][b][0] = osA[a][b][1] = 0.f;                                       \
        _Pragma("unroll")                                                        \
        for (int p = 0; p < 2; p++)                                              \
            ovA[a][b][p][0] = ovA[a][b][p][1] = ovA[a][b][p][2] = 0.f;           \
    }                                                                            \
    PATH_S(BP, 0, xs[m] * s0A, osA);                                             \
    {                                                                            \
        float t8a[2][2][2];                                                      \
        _Pragma("unroll")                                                        \
        for (int a = 0; a < 2; a++)                                              \
        _Pragma("unroll")                                                        \
        for (int b = 0; b < 2; b++) t8a[a][b][0] = t8a[a][b][1] = 0.f;           \
        PATH_S(BP, 1, xs[m] * m1_, t8a);                                         \
        _Pragma("unroll")                                                        \
        for (int mt = 0; mt < 2; mt++)                                           \
        _Pragma("unroll")                                                        \
        for (int h = 0; h < 2; h++) {                                            \
            int srcl = mt * 16 + h * 8 + r4;                                     \
            float sx = __shfl_sync(FULLMASK, s1x, srcl);                         \
            float sy = __shfl_sync(FULLMASK, s1y, srcl);                         \
            float sz = __shfl_sync(FULLMASK, s1z, srcl);                         \
            ovA[mt][h][0][0] += t8a[mt][h][0] * sx;                              \
            ovA[mt][h][1][0] += t8a[mt][h][1] * sx;                              \
            ovA[mt][h][0][1] += t8a[mt][h][0] * sy;                              \
            ovA[mt][h][1][1] += t8a[mt][h][1] * sy;                              \
            ovA[mt][h][0][2] += t8a[mt][h][0] * sz;                              \
            ovA[mt][h][1][2] += t8a[mt][h][1] * sz;                              \
        }                                                                        \
    }                                                                            \
    PATH_V(BP, 2, xv[m][0] * s0B, xv[m][1] * s0B, xv[m][2] * s0B);               \
    PATH_S(BP, 3, (xv[m][0] * s1x + xv[m][1] * s1y + xv[m][2] * s1z) * dA, osA); \
    PATH_V(BP, 4, (xv[m][1] * s1z - xv[m][2] * s1y) * cB,                        \
                  (xv[m][2] * s1x - xv[m][0] * s1z) * cB,                        \
                  (xv[m][0] * s1y - xv[m][1] * s1x) * cB);                       \
} while (0)

__global__ void __launch_bounds__(256, 2) fused_all(
    const float* __restrict__ na, const int* __restrict__ ei,
    const float* __restrict__ eattr, const float* __restrict__ esh,
    const float* __restrict__ kW1, const float* __restrict__ kW2,
    const float* __restrict__ vW1, const float* __restrict__ vW2,
    float* __restrict__ out) {
    extern __shared__ uint32_t smu[];
    const uint2* sW1k = (const uint2*)(smu + SW1K_OFF);
    const uint2* sW1v = (const uint2*)(smu + SW1V_OFF);
    const uint4* kB = (const uint4*)(smu + KB_OFF);
    const uint4* vB = (const uint4*)(smu + VB_OFF);

    const int tid = threadIdx.x;
    const int wid = tid >> 5;
    const int lane = tid & 31;
    const int r4 = lane >> 2;
    const int qc = lane & 3;

    // stage both W1s as tf32 b-frags (pre-scaled by 1/sqrt(16))
    for (int idx = tid; idx < 512; idx += 256) {
        int lane_ = idx & 31, kk = (idx >> 5) & 1, nt = idx >> 6;
        int r4_ = lane_ >> 2, qc_ = lane_ & 3;
        uint2 a, b;
        a.x = tf32r(kW1[(8 * kk + qc_) * 64 + 8 * nt + r4_] * 0.25f);
        a.y = tf32r(kW1[(8 * kk + 4 + qc_) * 64 + 8 * nt + r4_] * 0.25f);
        ((uint2*)(smu + SW1K_OFF))[idx] = a;
        b.x = tf32r(vW1[(8 * kk + qc_) * 64 + 8 * nt + r4_] * 0.25f);
        b.y = tf32r(vW1[(8 * kk + 4 + qc_) * 64 + 8 * nt + r4_] * 0.25f);
        ((uint2*)(smu + SW1V_OFF))[idx] = b;
    }
    // stage both W2s as fp16 b-frags
    for (int idx = tid; idx < 2560; idx += 256) {
        int lane_ = idx & 31;
        int kkp = (idx >> 5) & 1;
        int nt = (idx >> 6) & 7;
        int p = idx >> 9;
        int col = p * 64 + nt * 8 + (lane_ >> 2);
        int k0 = kkp * 32 + 2 * (lane_ & 3);
        int k1 = k0 + 16;
        uint4 v;
        v.x = pkh2(kW2[k0 * 320 + col],       kW2[(k0 + 1) * 320 + col]);
        v.y = pkh2(kW2[(k0 + 8) * 320 + col], kW2[(k0 + 9) * 320 + col]);
        v.z = pkh2(kW2[k1 * 320 + col],       kW2[(k1 + 1) * 320 + col]);
        v.w = pkh2(kW2[(k1 + 8) * 320 + col], kW2[(k1 + 9) * 320 + col]);
        ((uint4*)(smu + KB_OFF))[idx] = v;
        v.x = pkh2(vW2[k0 * 320 + col],       vW2[(k0 + 1) * 320 + col]);
        v.y = pkh2(vW2[(k0 + 8) * 320 + col], vW2[(k0 + 9) * 320 + col]);
        v.z = pkh2(vW2[k1 * 320 + col],       vW2[(k1 + 1) * 320 + col]);
        v.w = pkh2(vW2[(k1 + 8) * 320 + col], vW2[(k1 + 9) * 320 + col]);
        ((uint4*)(smu + VB_OFF))[idx] = v;
    }
    __syncthreads();   // only barrier in the kernel

    const int gw = blockIdx.x * 8 + wid;
    for (int c = gw; c < NCHUNKS; c += NWARPS) {
        const int e0 = c * 32;
        const int e = e0 + lane;

        // ---- layer-1 A fragments (shared by K and V phases) ----
        uint32_t a1f[2][2][4];
#pragma unroll
        for (int mt = 0; mt < 2; mt++)
#pragma unroll
            for (int kk = 0; kk < 2; kk++) {
                const float* eb0 = eattr + (size_t)(e0 + mt * 16 + r4) * 16 + 8 * kk + qc;
                const float* eb1 = eattr + (size_t)(e0 + mt * 16 + 8 + r4) * 16 + 8 * kk + qc;
                a1f[mt][kk][0] = tf32r(eb0[0]);
                a1f[mt][kk][1] = tf32r(eb1[0]);
                a1f[mt][kk][2] = tf32r(eb0[4]);
                a1f[mt][kk][3] = tf32r(eb1[4]);
            }

        // ---- per-edge features (lane owns edge e) ----
        int srcn = ei[e];
        int dst = ei[NE + e];
        float xs[8], xv[8][3];
        {
            const float4* xp = (const float4*)(na + (size_t)srcn * 32);
#pragma unroll
            for (int q = 0; q < 2; q++) {
                float4 v = xp[q];
                xs[q * 4 + 0] = v.x; xs[q * 4 + 1] = v.y;
                xs[q * 4 + 2] = v.z; xs[q * 4 + 3] = v.w;
            }
#pragma unroll
            for (int q = 0; q < 6; q++) {
                float4 v = xp[2 + q];
                ((float*)xv)[q * 4 + 0] = v.x; ((float*)xv)[q * 4 + 1] = v.y;
                ((float*)xv)[q * 4 + 2] = v.z; ((float*)xv)[q * 4 + 3] = v.w;
            }
        }
        float4 sh = *(const float4*)(esh + (size_t)e * 4);
        float s0 = sh.x, s1x = sh.y, s1y = sh.z, s1z = sh.w;

        uint32_t aF[4][8];
        float osA[2][2][2];
        float ovA[2][2][2][3];

        // ================= K phase =================
        RUN_L1(sW1k);
        RUN_PATHS(kB, OUTS_SC * LOGIT_SC, OUTV_SC * LOGIT_VSC * LOGIT_SC);

        float ex[2][2];
#pragma unroll
        for (int mt = 0; mt < 2; mt++)
#pragma unroll
            for (int h = 0; h < 2; h++) {
                int srcl = mt * 16 + h * 8 + r4;
                int dstr = __shfl_sync(FULLMASK, dst, srcl);
                const float* ap = g_a + (size_t)dstr * 32;
                float2 a01 = *(const float2*)(ap + 2 * qc);
                float lp = a01.x * osA[mt][h][0] + a01.y * osA[mt][h][1];
                float2 v0 = *(const float2*)(ap + 8 + 6 * qc);
                float2 v1 = *(const float2*)(ap + 8 + 6 * qc + 2);
                float2 v2 = *(const float2*)(ap + 8 + 6 * qc + 4);
                lp += v0.x * ovA[mt][h][0][0] + v0.y * ovA[mt][h][0][1];
                lp += v1.x * ovA[mt][h][0][2] + v1.y * ovA[mt][h][1][0];
                lp += v2.x * ovA[mt][h][1][1] + v2.y * ovA[mt][h][1][2];
                lp += __shfl_xor_sync(FULLMASK, lp, 1);
                lp += __shfl_xor_sync(FULLMASK, lp, 2);
                float exv = __expf(lp);
                ex[mt][h] = exv;
                if (qc == 0) red2(&g_zc[(size_t)dstr * 2], exv, 1.0f);
            }

        // hand att = sqrt(ex of MY edge) back to the owner lane
        float att = 0.f;
#pragma unroll
        for (int mt = 0; mt < 2; mt++)
#pragma unroll
            for (int h = 0; h < 2; h++) {
                float v = __shfl_sync(FULLMASK, ex[mt][h], 4 * (lane & 7));
                if ((lane >> 3) == mt * 2 + h) att = sqrtf(v);
            }

        // ================= V phase =================
        RUN_L1(sW1v);
        RUN_PATHS(vB, att * OUTS_SC, att * OUTV_SC);

#pragma unroll
        for (int mt = 0; mt < 2; mt++)
#pragma unroll
            for (int h = 0; h < 2; h++) {
                int srcl = mt * 16 + h * 8 + r4;
                int dstr = __shfl_sync(FULLMASK, dst, srcl);
                float* ob = out + (size_t)dstr * 32;
                red2(ob + 2 * qc, osA[mt][h][0], osA[mt][h][1]);
                red2(ob + 8 + 6 * qc,     ovA[mt][h][0][0], ovA[mt][h][0][1]);
                red2(ob + 8 + 6 * qc + 2, ovA[mt][h][0][2], ovA[mt][h][1][0]);
                red2(ob + 8 + 6 * qc + 4, ovA[mt][h][1][1], ovA[mt][h][1][2]);
            }
    }
}

extern "C" void kernel_launch(void* const* d_in, const int* in_sizes, int n_in,
                              void* d_out, int out_size) {
    const float* na    = (const float*)d_in[0];
    const int*   ei    = (const int*)d_in[1];
    const float* eattr = (const float*)d_in[2];
    const float* esh   = (const float*)d_in[3];
    const float* Wq0   = (const float*)d_in[4];
    const float* Wq1   = (const float*)d_in[5];
    const float* kW1   = (const float*)d_in[6];
    const float* kW2   = (const float*)d_in[7];
    const float* vW1   = (const float*)d_in[8];
    const float* vW2   = (const float*)d_in[9];
    const float* Wd0   = (const float*)d_in[10];
    const float* Wd1   = (const float*)d_in[11];
    float* out = (float*)d_out;

    cudaFuncSetAttribute(fused_all, cudaFuncAttributeMaxDynamicSharedMemorySize, SMEM_BYTES);

    // zero output + z/cnt via DMA (graph-capturable, no kernel launch)
    void* zc_ptr = nullptr;
    cudaGetSymbolAddress(&zc_ptr, g_zc);
    cudaMemsetAsync(d_out, 0, (size_t)NN * 32 * sizeof(float));
    cudaMemsetAsync(zc_ptr, 0, (size_t)NN * 2 * sizeof(float));

    node_prep<<<(NN + 63) / 64, 256>>>(na, Wq0, Wq1, Wd0, Wd1);
    fused_all<<<GRID_FA, 256, SMEM_BYTES>>>(na, ei, eattr, esh, kW1, kW2, vW1, vW2, out);
    finalize<<<(NN * 8 + 255) / 256, 256>>>(out);
}